// round 11
// baseline (speedup 1.0000x reference)
#include <cuda_runtime.h>

// ---------------------------------------------------------------------------
// Compile-time Cayley sign for Cl(p=3, q=1, r=0): 16 blades.
// e_i * e_j = sign(i,j) * e_{i XOR j}
// sign = (-1)^{# pairs (p in i, q in j) with p > q} * metric factor,
// metric = (+1,+1,+1,-1): generator 3 (bit 3) squares to -1.
// ---------------------------------------------------------------------------

__host__ __device__ constexpr int ct_popc(unsigned x) {
    int c = 0;
    while (x) { c += (int)(x & 1u); x >>= 1; }
    return c;
}

__host__ __device__ constexpr float ct_sign(int i, int j) {
    int swaps = 0;
    unsigned a = ((unsigned)i) >> 1;
    while (a) { swaps += ct_popc(a & (unsigned)j); a >>= 1; }
    float s = (swaps & 1) ? -1.0f : 1.0f;
    if ((i & j) & 0x8) s = -s;   // e3^2 = -1
    return s;
}

// Flat-expanded 256-term bilinear form (compile-time indices + signs).
template <int I, int J>
__device__ __forceinline__ void do_term(const float (&A)[16],
                                        const float (&B)[16],
                                        float (&O)[16]) {
    constexpr float s = ct_sign(I, J);
    O[I ^ J] = fmaf(s * A[I], B[J], O[I ^ J]);
}

#define GP_T(I, J) do_term<(I), (J)>(A, B, O);
#define GP_ROW(I)                                                         \
    GP_T(I, 0)  GP_T(I, 1)  GP_T(I, 2)  GP_T(I, 3)                        \
    GP_T(I, 4)  GP_T(I, 5)  GP_T(I, 6)  GP_T(I, 7)                        \
    GP_T(I, 8)  GP_T(I, 9)  GP_T(I, 10) GP_T(I, 11)                       \
    GP_T(I, 12) GP_T(I, 13) GP_T(I, 14) GP_T(I, 15)

__device__ __forceinline__ void do_all(const float (&A)[16],
                                       const float (&B)[16],
                                       float (&O)[16]) {
    GP_ROW(0)  GP_ROW(1)  GP_ROW(2)  GP_ROW(3)
    GP_ROW(4)  GP_ROW(5)  GP_ROW(6)  GP_ROW(7)
    GP_ROW(8)  GP_ROW(9)  GP_ROW(10) GP_ROW(11)
    GP_ROW(12) GP_ROW(13) GP_ROW(14) GP_ROW(15)
}

// ---------------------------------------------------------------------------
// SMEM-staged kernel. R6 profile: L1=76% > DRAM=62% — per-thread 64B rows
// make every LDG.128/STG.128 span 16 L1 lines (4x wavefront cost). Here all
// global traffic is lane-contiguous float4 (4 lines per warp-instruction),
// transposed through shared memory.
// Row stride in smem = 20 floats (80B): 16B-aligned for LDS/STS.128, and the
// x5 16B-unit stride distributes quads evenly over the 8 crossbar groups.
// ---------------------------------------------------------------------------

constexpr int ROWS_PER_BLK = 256;
constexpr int ROW_PAD = 20;          // floats per row in smem

__global__ void __launch_bounds__(256)
clifford_gp_kernel(const float4* __restrict__ a4,
                   const float4* __restrict__ b4,
                   float4* __restrict__ o4,
                   int n_rows) {
    __shared__ float sa[ROWS_PER_BLK * ROW_PAD];
    __shared__ float sb[ROWS_PER_BLK * ROW_PAD];

    const int tid = threadIdx.x;
    const long base4 = (long)blockIdx.x * (ROWS_PER_BLK * 4);  // float4 units
    const long total4 = (long)n_rows * 4;

    // ---- coalesced load: linear float4s -> padded smem rows ----
#pragma unroll
    for (int k = 0; k < 4; k++) {
        int lin = k * 256 + tid;                 // float4 index within block
        long g = base4 + lin;
        if (g < total4) {
            float4 va = a4[g];
            float4 vb = b4[g];
            int row = lin >> 2;
            int q   = lin & 3;
            *reinterpret_cast<float4*>(&sa[row * ROW_PAD + q * 4]) = va;
            *reinterpret_cast<float4*>(&sb[row * ROW_PAD + q * 4]) = vb;
        }
    }
    __syncthreads();

    // ---- per-thread row compute ----
    float A[16], B[16];
#pragma unroll
    for (int k = 0; k < 4; k++) {
        *reinterpret_cast<float4*>(&A[k * 4]) =
            *reinterpret_cast<const float4*>(&sa[tid * ROW_PAD + k * 4]);
        *reinterpret_cast<float4*>(&B[k * 4]) =
            *reinterpret_cast<const float4*>(&sb[tid * ROW_PAD + k * 4]);
    }

    float O[16] = {};
    do_all(A, B, O);

    // nan -> 0, then clip to [-1000, 1000]
#pragma unroll
    for (int c = 0; c < 16; c++) {
        float v = O[c];
        if (v != v) v = 0.0f;
        v = fminf(fmaxf(v, -1000.0f), 1000.0f);
        O[c] = v;
    }

    // ---- stage output back through smem (reuse sa), coalesced store ----
    __syncthreads();   // everyone done reading sa
#pragma unroll
    for (int k = 0; k < 4; k++) {
        *reinterpret_cast<float4*>(&sa[tid * ROW_PAD + k * 4]) =
            make_float4(O[k * 4 + 0], O[k * 4 + 1], O[k * 4 + 2], O[k * 4 + 3]);
    }
    __syncthreads();

#pragma unroll
    for (int k = 0; k < 4; k++) {
        int lin = k * 256 + tid;
        long g = base4 + lin;
        if (g < total4) {
            int row = lin >> 2;
            int q   = lin & 3;
            o4[g] = *reinterpret_cast<const float4*>(&sa[row * ROW_PAD + q * 4]);
        }
    }
}

extern "C" void kernel_launch(void* const* d_in, const int* in_sizes, int n_in,
                              void* d_out, int out_size) {
    const float4* a4 = (const float4*)d_in[0];
    const float4* b4 = (const float4*)d_in[1];
    float4* o4 = (float4*)d_out;

    int n_rows = in_sizes[0] / 16;
    int blocks = (n_rows + ROWS_PER_BLK - 1) / ROWS_PER_BLK;
    clifford_gp_kernel<<<blocks, 256>>>(a4, b4, o4, n_rows);
}